// round 6
// baseline (speedup 1.0000x reference)
#include <cuda_runtime.h>

#define T_STEPS 2000
#define BATCH   256
#define SEQ     10000
#define KW      5

typedef unsigned long long ull;

// Gate pre-activations a_x[t][b][j], stored so float2 at (t*256+b)*32 + l =
// { a[j=l], a[j=l+32] } (lane l of scan warp owns gate rows l and l+32).
__device__ float g_ax[(size_t)T_STEPS * BATCH * 64];
__device__ float g_P[80];
__device__ float g_N[80];
__device__ int   g_bmnz;
// Column-centered weights (LN mean folded into weights).
__device__ float g_WhC[64 * 16];
__device__ float g_WxC[64 * 16];

__device__ __forceinline__ float sigf(float x) {
    return __fdividef(1.0f, 1.0f + __expf(-x));
}

// ---- f32x2 packed helpers (sm_103a) --------------------------------------
__device__ __forceinline__ ull pk2(float lo, float hi) {
    ull r; asm("mov.b64 %0, {%1, %2};" : "=l"(r) : "f"(lo), "f"(hi)); return r;
}
__device__ __forceinline__ void upk2(float& lo, float& hi, ull v) {
    asm("mov.b64 {%0, %1}, %2;" : "=f"(lo), "=f"(hi) : "l"(v));
}
__device__ __forceinline__ ull ffma2(ull a, ull b, ull c) {
    ull r; asm("fma.rn.f32x2 %0, %1, %2, %3;" : "=l"(r) : "l"(a), "l"(b), "l"(c)); return r;
}
__device__ __forceinline__ ull fadd2(ull a, ull b) {
    ull r; asm("add.rn.f32x2 %0, %1, %2;" : "=l"(r) : "l"(a), "l"(b)); return r;
}
__device__ __forceinline__ ull fmul2(ull a, ull b) {
    ull r; asm("mul.rn.f32x2 %0, %1, %2;" : "=l"(r) : "l"(a), "l"(b)); return r;
}

// ---------------------------------------------------------------------------
// Init: P/N conv collapse + column-centered WhC / WxC.
// ---------------------------------------------------------------------------
__global__ void init_kernel(const float* __restrict__ Wm,
                            const float* __restrict__ bm,
                            const float* __restrict__ Wc,
                            const float* __restrict__ Wh,
                            const float* __restrict__ Wx)
{
    __shared__ float cmh[16], cmx[16];
    int tid = threadIdx.x;
    if (tid == 0) {
        int nz = 0;
        for (int i = 0; i < 16; i++) if (bm[i] != 0.0f) nz = 1;
        g_bmnz = nz;
    }
    if (tid < 16) {
        float sh = 0.0f, sx = 0.0f;
        for (int j = 0; j < 64; j++) {
            sh += Wh[j * 16 + tid];
            sx += Wx[j * 16 + tid];
        }
        cmh[tid] = sh * (1.0f / 64.0f);
        cmx[tid] = sx * (1.0f / 64.0f);
    }
    if (tid < 80) {
        int o = tid / 5, k = tid % 5;
        float p = 0.0f, n = 0.0f;
        for (int i = 0; i < 16; i++) {
            float w = Wm[i];
            float c = Wc[o * 80 + i * 5 + k];
            if (w > 0.0f) p = fmaf(c, w, p);
            else if (w < 0.0f) n = fmaf(c, w, n);
        }
        g_P[tid] = p;
        g_N[tid] = n;
    }
    __syncthreads();
    for (int idx = tid; idx < 1024; idx += blockDim.x) {
        int i = idx & 15;
        g_WhC[idx] = Wh[idx] - cmh[i];
        g_WxC[idx] = Wx[idx] - cmx[i];
    }
}

// ---------------------------------------------------------------------------
// Pre-pass: one THREAD per (t, b); warp covers 32 consecutive t of one b.
// Centered WxC -> no mean reduction. Packed f32x2 matvec + LN.
// ---------------------------------------------------------------------------
__global__ void __launch_bounds__(128) prepass_kernel(
    const float* __restrict__ x,  const float* __restrict__ Wm,
    const float* __restrict__ bm, const float* __restrict__ Wc,
    const float* __restrict__ bconv,
    const float* __restrict__ gx, const float* __restrict__ bx,
    const float* __restrict__ bg)
{
    __shared__ float sP[80], sN[80], sbc[16];
    __shared__ float sWm[16], sbm[16];
    __shared__ float sWcT[80 * 16];                 // fallback path only
    __shared__ ull sWxT2[16][32];                   // [o][l] = (WxC[l][o], WxC[l+32][o])
    __shared__ ull sgx2[32], sbxg2[32];
    __shared__ float2 stage[4][32][33];             // [warp][item][pair] (+pad)

    for (int i = threadIdx.x; i < 80; i += blockDim.x) {
        sP[i] = g_P[i]; sN[i] = g_N[i];
    }
    for (int i = threadIdx.x; i < 16; i += blockDim.x) {
        sbc[i] = bconv[i]; sWm[i] = Wm[i]; sbm[i] = bm[i];
    }
    for (int i = threadIdx.x; i < 80 * 16; i += blockDim.x) {
        int ik = i >> 4, o = i & 15;
        sWcT[i] = Wc[o * 80 + ik];
    }
    for (int i = threadIdx.x; i < 16 * 32; i += blockDim.x) {
        int o = i >> 5, l = i & 31;
        sWxT2[o][l] = pk2(g_WxC[l * 16 + o], g_WxC[(l + 32) * 16 + o]);
    }
    for (int i = threadIdx.x; i < 32; i += blockDim.x) {
        sgx2[i]  = pk2(gx[i], gx[i + 32]);
        sbxg2[i] = pk2(bx[i] + bg[i], bx[i + 32] + bg[i + 32]);
    }
    __syncthreads();

    const int bmnz = g_bmnz;
    int lane = threadIdx.x & 31;
    int wrp  = threadIdx.x >> 5;
    int b    = blockIdx.y;
    int tbase = blockIdx.x * 128 + wrp * 32;
    int t     = tbase + lane;
    int tt = (t < T_STEPS) ? t : 0;

    float xt[16];
    #pragma unroll
    for (int o = 0; o < 16; o++) xt[o] = sbc[o];

    if (!bmnz) {
        #pragma unroll
        for (int k = 0; k < KW; k++) {
            float xk = __ldg(&x[b * SEQ + tt * KW + k]);
            const float* PN = (xk > 0.0f) ? sP : sN;
            #pragma unroll
            for (int o = 0; o < 16; o++)
                xt[o] = fmaf(xk, PN[o * 5 + k], xt[o]);
        }
    } else {
        #pragma unroll
        for (int k = 0; k < KW; k++) {
            float xk = __ldg(&x[b * SEQ + tt * KW + k]);
            #pragma unroll
            for (int i = 0; i < 16; i++) {
                float f = fmaxf(fmaf(xk, sWm[i], sbm[i]), 0.0f);
                const float4* wr = (const float4*)&sWcT[(i * KW + k) * 16];
                #pragma unroll
                for (int o4 = 0; o4 < 4; o4++) {
                    float4 w = wr[o4];
                    xt[o4 * 4 + 0] = fmaf(w.x, f, xt[o4 * 4 + 0]);
                    xt[o4 * 4 + 1] = fmaf(w.y, f, xt[o4 * 4 + 1]);
                    xt[o4 * 4 + 2] = fmaf(w.z, f, xt[o4 * 4 + 2]);
                    xt[o4 * 4 + 3] = fmaf(w.w, f, xt[o4 * 4 + 3]);
                }
            }
        }
    }
    #pragma unroll
    for (int o = 0; o < 16; o++) xt[o] = sigf(xt[o]);

    // y' = xt @ WxC^T, packed; mean(y') == 0 by construction
    ull y2[32];
    #pragma unroll
    for (int l = 0; l < 32; l++) y2[l] = 0ull;
    #pragma unroll
    for (int o = 0; o < 16; o++) {
        ull x2 = pk2(xt[o], xt[o]);
        #pragma unroll
        for (int l = 0; l < 32; l++)
            y2[l] = ffma2(sWxT2[o][l], x2, y2[l]);
    }

    ull q2a = 0ull, q2b = 0ull;
    #pragma unroll
    for (int l = 0; l < 32; l += 2) {
        q2a = ffma2(y2[l],     y2[l],     q2a);
        q2b = ffma2(y2[l + 1], y2[l + 1], q2b);
    }
    float qa, qb, qc, qd;
    upk2(qa, qb, q2a); upk2(qc, qd, q2b);
    float q = (qa + qb) + (qc + qd);
    float r = rsqrtf(q * (1.0f / 64.0f) + 1e-5f);

    ull r2 = pk2(r, r);
    #pragma unroll
    for (int l = 0; l < 32; l++) {
        ull tnorm = fmul2(y2[l], r2);
        ull a2    = ffma2(tnorm, sgx2[l], sbxg2[l]);
        float a0, a1; upk2(a0, a1, a2);
        stage[wrp][lane][l] = make_float2(a0, a1);
    }
    __syncwarp();

    float2* gax2 = (float2*)g_ax;
    #pragma unroll 4
    for (int k = 0; k < 32; k++) {
        int tk = tbase + k;
        if (tk < T_STEPS)
            gax2[((size_t)tk * 256 + b) * 32 + lane] = stage[wrp][k][lane];
    }
}

// ---------------------------------------------------------------------------
// Sequential LSTM scan. ONE warp = ONE batch row.
//   lane l: gate rows ja=l (i|f), jb=l+32 (g|o), packed (lo=ja, hi=jb).
//   h published DUPLICATED as float2(h,h) -> matvec = 16 ffma2 on LDS.128 data.
//   var gather: 32 partials -> 8 LDS.128 + fadd2 tree.
//   LN16: upper lanes publish (c, c^2) -> ONE fadd2 tree gives both stats.
// ---------------------------------------------------------------------------
__global__ void __launch_bounds__(32) lstm_seq_kernel(
    const float* __restrict__ gh,   const float* __restrict__ bh,
    const float* __restrict__ gc,   const float* __restrict__ bc,
    const float* __restrict__ Wcls, const float* __restrict__ bcls,
    const float* __restrict__ h0,   const float* __restrict__ c0,
    float* __restrict__ out)
{
    const unsigned ALL = 0xffffffffu;
    int lane  = threadIdx.x;
    int m     = lane & 15;
    bool upper = lane >= 16;
    int row   = blockIdx.x;

    __shared__ float2 shd[16];    // (h, h) duplicated
    __shared__ float  sqp[32];    // q partials
    __shared__ float2 scq[16];    // (c, c^2)

    // packed weights: w2[i] = (WhC[ja][i], WhC[jb][i])
    ull w2[16];
    #pragma unroll
    for (int i = 0; i < 16; i++)
        w2[i] = pk2(g_WhC[lane * 16 + i], g_WhC[(lane + 32) * 16 + i]);

    ull gh2 = pk2(gh[lane], gh[lane + 32]);
    ull bh2 = pk2(bh[lane], bh[lane + 32]);
    float gcm = gc[m], bcm = bc[m];

    float h = h0[row * 16 + m];
    float c = c0[row * 16 + m];
    if (upper) shd[m] = make_float2(h, h);
    __syncwarp();

    const ull* ax = (const ull*)g_ax;     // each = (a[ja], a[jb])
    int base = row * 32 + lane;
    const int stride = BATCH * 32;
    ull p0 = ax[base];
    ull p1 = ax[base + stride];

    for (int t = 0; t < T_STEPS; t++) {
        const ull* hp = (const ull*)shd;  // 16 packed (h,h)

        ull cur = p0;
        p0 = p1;
        if (t + 2 < T_STEPS) p1 = ax[base + (t + 2) * stride];

        // packed matvec: y2 = sum_i w2[i] * (h_i, h_i); 4 chains of 4
        ull a0 = fmul2(w2[0], hp[0]);
        ull a1 = fmul2(w2[1], hp[1]);
        ull a2 = fmul2(w2[2], hp[2]);
        ull a3 = fmul2(w2[3], hp[3]);
        a0 = ffma2(w2[4],  hp[4],  a0);
        a1 = ffma2(w2[5],  hp[5],  a1);
        a2 = ffma2(w2[6],  hp[6],  a2);
        a3 = ffma2(w2[7],  hp[7],  a3);
        a0 = ffma2(w2[8],  hp[8],  a0);
        a1 = ffma2(w2[9],  hp[9],  a1);
        a2 = ffma2(w2[10], hp[10], a2);
        a3 = ffma2(w2[11], hp[11], a3);
        a0 = ffma2(w2[12], hp[12], a0);
        a1 = ffma2(w2[13], hp[13], a1);
        a2 = ffma2(w2[14], hp[14], a2);
        a3 = ffma2(w2[15], hp[15], a3);
        ull y2 = fadd2(fadd2(a0, a1), fadd2(a2, a3));

        // var partial: ya^2 + yb^2
        float ya, yb; upk2(ya, yb, y2);
        sqp[lane] = fmaf(ya, ya, yb * yb);
        __syncwarp();

        // gather: 32 floats = 16 u64, fadd2 tree
        const ull* qv = (const ull*)sqp;
        ull t0 = fadd2(qv[0],  qv[1]);
        ull t1 = fadd2(qv[2],  qv[3]);
        ull t2 = fadd2(qv[4],  qv[5]);
        ull t3 = fadd2(qv[6],  qv[7]);
        ull t4 = fadd2(qv[8],  qv[9]);
        ull t5 = fadd2(qv[10], qv[11]);
        ull t6 = fadd2(qv[12], qv[13]);
        ull t7 = fadd2(qv[14], qv[15]);
        t0 = fadd2(t0, t1); t2 = fadd2(t2, t3);
        t4 = fadd2(t4, t5); t6 = fadd2(t6, t7);
        t0 = fadd2(fadd2(t0, t2), fadd2(t4, t6));
        float qlo, qhi; upk2(qlo, qhi, t0);
        float r = rsqrtf((qlo + qhi) * (1.0f / 64.0f) + 1e-5f);

        // gates packed: g2 = (y2 * r) * gh2 + bh2 + cur
        ull r2 = pk2(r, r);
        ull g2 = fadd2(ffma2(fmul2(y2, r2), gh2, bh2), cur);
        float ga, gb; upk2(ga, gb, g2);

        float u1 = sigf(ga);                          // sig(i) | sig(f)
        float u2 = sigf(upper ? gb : (2.0f * gb));    // sig(o) | sig(2g)
        float Aval = u1 * fmaf(2.0f, u2, -1.0f);      // lower: sig(i)*tanh(g)
        float A = __shfl_xor_sync(ALL, Aval, 16);

        c = fmaf(u1, c, A);                           // valid on upper lanes
        if (upper) scq[m] = make_float2(c, c * c);
        __syncwarp();

        // LN16 stats: one tree over (c, c^2) pairs gives (sum, sumsq)
        const ull* cv = (const ull*)scq;
        ull s0 = fadd2(cv[0],  cv[1]);
        ull s1 = fadd2(cv[2],  cv[3]);
        ull s2 = fadd2(cv[4],  cv[5]);
        ull s3 = fadd2(cv[6],  cv[7]);
        ull s4 = fadd2(cv[8],  cv[9]);
        ull s5 = fadd2(cv[10], cv[11]);
        ull s6 = fadd2(cv[12], cv[13]);
        ull s7 = fadd2(cv[14], cv[15]);
        s0 = fadd2(s0, s1); s2 = fadd2(s2, s3);
        s4 = fadd2(s4, s5); s6 = fadd2(s6, s7);
        s0 = fadd2(fadd2(s0, s2), fadd2(s4, s6));
        float sc, qc; upk2(sc, qc, s0);

        float mc = sc * (1.0f / 16.0f);
        float vc = fmaf(-mc, mc, qc * (1.0f / 16.0f));
        float rc = rsqrtf(vc + 1e-5f);
        float cn = fmaf((c - mc) * rc, gcm, bcm);
        float u  = sigf(2.0f * cn);                   // tanh(cn) = 2u - 1
        h = fmaf(u2 + u2, u, -u2);                    // u2 * (2u - 1)
        if (upper) shd[m] = make_float2(h, h);
        __syncwarp();
    }

    // classifier: sigmoid(h . W_cls + b_cls)  (h valid on upper lanes)
    float v = upper ? h * Wcls[m] : 0.0f;
    #pragma unroll
    for (int d = 16; d >= 1; d >>= 1)
        v += __shfl_xor_sync(ALL, v, d);
    if (lane == 0)
        out[row] = sigf(v + bcls[0]);
}

// ---------------------------------------------------------------------------
extern "C" void kernel_launch(void* const* d_in, const int* in_sizes, int n_in,
                              void* d_out, int out_size)
{
    const float* x     = (const float*)d_in[0];
    const float* Wm    = (const float*)d_in[1];
    const float* bm    = (const float*)d_in[2];
    const float* Wc    = (const float*)d_in[3];
    const float* bconv = (const float*)d_in[4];
    const float* Wx    = (const float*)d_in[5];
    const float* Wh    = (const float*)d_in[6];
    const float* bg    = (const float*)d_in[7];
    const float* gx    = (const float*)d_in[8];
    const float* bx    = (const float*)d_in[9];
    const float* gh    = (const float*)d_in[10];
    const float* bh    = (const float*)d_in[11];
    const float* gc    = (const float*)d_in[12];
    const float* bc    = (const float*)d_in[13];
    const float* Wcls  = (const float*)d_in[14];
    const float* bcls  = (const float*)d_in[15];
    const float* h0    = (const float*)d_in[16];
    const float* c0    = (const float*)d_in[17];
    float* out = (float*)d_out;

    init_kernel<<<1, 128>>>(Wm, bm, Wc, Wh, Wx);
    dim3 pgrid((T_STEPS + 127) / 128, BATCH);
    prepass_kernel<<<pgrid, 128>>>(x, Wm, bm, Wc, bconv, gx, bx, bg);
    lstm_seq_kernel<<<BATCH, 32>>>(gh, bh, gc, bc, Wcls, bcls, h0, c0, out);
}

// round 7
// speedup vs baseline: 1.0132x; 1.0132x over previous
#include <cuda_runtime.h>

#define T_STEPS 2000
#define BATCH   256
#define SEQ     10000
#define KW      5

typedef unsigned long long ull;

// Gate pre-activations a_x[t][b][j], stored so float2 at (t*256+b)*32 + l =
// { a[j=l], a[j=l+32] } (lane l of scan warp owns gate rows l and l+32).
__device__ float g_ax[(size_t)T_STEPS * BATCH * 64];
__device__ float g_P[80];
__device__ float g_N[80];
__device__ int   g_bmnz;
// Column-centered weights (LN mean folded into weights).
__device__ float g_WhC[64 * 16];
__device__ float g_WxC[64 * 16];

__device__ __forceinline__ float sigf(float x) {
    return __fdividef(1.0f, 1.0f + __expf(-x));
}

// ---- f32x2 packed helpers (sm_103a) --------------------------------------
__device__ __forceinline__ ull pk2(float lo, float hi) {
    ull r; asm("mov.b64 %0, {%1, %2};" : "=l"(r) : "f"(lo), "f"(hi)); return r;
}
__device__ __forceinline__ void upk2(float& lo, float& hi, ull v) {
    asm("mov.b64 {%0, %1}, %2;" : "=f"(lo), "=f"(hi) : "l"(v));
}
__device__ __forceinline__ ull ffma2(ull a, ull b, ull c) {
    ull r; asm("fma.rn.f32x2 %0, %1, %2, %3;" : "=l"(r) : "l"(a), "l"(b), "l"(c)); return r;
}
__device__ __forceinline__ ull fadd2(ull a, ull b) {
    ull r; asm("add.rn.f32x2 %0, %1, %2;" : "=l"(r) : "l"(a), "l"(b)); return r;
}
__device__ __forceinline__ ull fmul2(ull a, ull b) {
    ull r; asm("mul.rn.f32x2 %0, %1, %2;" : "=l"(r) : "l"(a), "l"(b)); return r;
}

// ---------------------------------------------------------------------------
// Init: P/N conv collapse + column-centered WhC / WxC.
// ---------------------------------------------------------------------------
__global__ void init_kernel(const float* __restrict__ Wm,
                            const float* __restrict__ bm,
                            const float* __restrict__ Wc,
                            const float* __restrict__ Wh,
                            const float* __restrict__ Wx)
{
    __shared__ float cmh[16], cmx[16];
    int tid = threadIdx.x;
    if (tid == 0) {
        int nz = 0;
        for (int i = 0; i < 16; i++) if (bm[i] != 0.0f) nz = 1;
        g_bmnz = nz;
    }
    if (tid < 16) {
        float sh = 0.0f, sx = 0.0f;
        for (int j = 0; j < 64; j++) {
            sh += Wh[j * 16 + tid];
            sx += Wx[j * 16 + tid];
        }
        cmh[tid] = sh * (1.0f / 64.0f);
        cmx[tid] = sx * (1.0f / 64.0f);
    }
    if (tid < 80) {
        int o = tid / 5, k = tid % 5;
        float p = 0.0f, n = 0.0f;
        for (int i = 0; i < 16; i++) {
            float w = Wm[i];
            float c = Wc[o * 80 + i * 5 + k];
            if (w > 0.0f) p = fmaf(c, w, p);
            else if (w < 0.0f) n = fmaf(c, w, n);
        }
        g_P[tid] = p;
        g_N[tid] = n;
    }
    __syncthreads();
    for (int idx = tid; idx < 1024; idx += blockDim.x) {
        int i = idx & 15;
        g_WhC[idx] = Wh[idx] - cmh[i];
        g_WxC[idx] = Wx[idx] - cmx[i];
    }
}

// ---------------------------------------------------------------------------
// Pre-pass: one THREAD per (t, b); warp covers 32 consecutive t of one b.
// Centered WxC -> no mean reduction. Packed f32x2 matvec + LN.
// ---------------------------------------------------------------------------
__global__ void __launch_bounds__(128) prepass_kernel(
    const float* __restrict__ x,  const float* __restrict__ Wm,
    const float* __restrict__ bm, const float* __restrict__ Wc,
    const float* __restrict__ bconv,
    const float* __restrict__ gx, const float* __restrict__ bx,
    const float* __restrict__ bg)
{
    __shared__ float sP[80], sN[80], sbc[16];
    __shared__ float sWm[16], sbm[16];
    __shared__ float sWcT[80 * 16];                 // fallback path only
    __shared__ ull sWxT2[16][32];                   // [o][l] = (WxC[l][o], WxC[l+32][o])
    __shared__ ull sgx2[32], sbxg2[32];
    __shared__ float2 stage[4][32][33];             // [warp][item][pair] (+pad)

    for (int i = threadIdx.x; i < 80; i += blockDim.x) {
        sP[i] = g_P[i]; sN[i] = g_N[i];
    }
    for (int i = threadIdx.x; i < 16; i += blockDim.x) {
        sbc[i] = bconv[i]; sWm[i] = Wm[i]; sbm[i] = bm[i];
    }
    for (int i = threadIdx.x; i < 80 * 16; i += blockDim.x) {
        int ik = i >> 4, o = i & 15;
        sWcT[i] = Wc[o * 80 + ik];
    }
    for (int i = threadIdx.x; i < 16 * 32; i += blockDim.x) {
        int o = i >> 5, l = i & 31;
        sWxT2[o][l] = pk2(g_WxC[l * 16 + o], g_WxC[(l + 32) * 16 + o]);
    }
    for (int i = threadIdx.x; i < 32; i += blockDim.x) {
        sgx2[i]  = pk2(gx[i], gx[i + 32]);
        sbxg2[i] = pk2(bx[i] + bg[i], bx[i + 32] + bg[i + 32]);
    }
    __syncthreads();

    const int bmnz = g_bmnz;
    int lane = threadIdx.x & 31;
    int wrp  = threadIdx.x >> 5;
    int b    = blockIdx.y;
    int tbase = blockIdx.x * 128 + wrp * 32;
    int t     = tbase + lane;
    int tt = (t < T_STEPS) ? t : 0;

    float xt[16];
    #pragma unroll
    for (int o = 0; o < 16; o++) xt[o] = sbc[o];

    if (!bmnz) {
        #pragma unroll
        for (int k = 0; k < KW; k++) {
            float xk = __ldg(&x[b * SEQ + tt * KW + k]);
            const float* PN = (xk > 0.0f) ? sP : sN;
            #pragma unroll
            for (int o = 0; o < 16; o++)
                xt[o] = fmaf(xk, PN[o * 5 + k], xt[o]);
        }
    } else {
        #pragma unroll
        for (int k = 0; k < KW; k++) {
            float xk = __ldg(&x[b * SEQ + tt * KW + k]);
            #pragma unroll
            for (int i = 0; i < 16; i++) {
                float f = fmaxf(fmaf(xk, sWm[i], sbm[i]), 0.0f);
                const float4* wr = (const float4*)&sWcT[(i * KW + k) * 16];
                #pragma unroll
                for (int o4 = 0; o4 < 4; o4++) {
                    float4 w = wr[o4];
                    xt[o4 * 4 + 0] = fmaf(w.x, f, xt[o4 * 4 + 0]);
                    xt[o4 * 4 + 1] = fmaf(w.y, f, xt[o4 * 4 + 1]);
                    xt[o4 * 4 + 2] = fmaf(w.z, f, xt[o4 * 4 + 2]);
                    xt[o4 * 4 + 3] = fmaf(w.w, f, xt[o4 * 4 + 3]);
                }
            }
        }
    }
    #pragma unroll
    for (int o = 0; o < 16; o++) xt[o] = sigf(xt[o]);

    // y' = xt @ WxC^T, packed; mean(y') == 0 by construction
    ull y2[32];
    #pragma unroll
    for (int l = 0; l < 32; l++) y2[l] = 0ull;
    #pragma unroll
    for (int o = 0; o < 16; o++) {
        ull x2 = pk2(xt[o], xt[o]);
        #pragma unroll
        for (int l = 0; l < 32; l++)
            y2[l] = ffma2(sWxT2[o][l], x2, y2[l]);
    }

    ull q2a = 0ull, q2b = 0ull;
    #pragma unroll
    for (int l = 0; l < 32; l += 2) {
        q2a = ffma2(y2[l],     y2[l],     q2a);
        q2b = ffma2(y2[l + 1], y2[l + 1], q2b);
    }
    float qa, qb, qc, qd;
    upk2(qa, qb, q2a); upk2(qc, qd, q2b);
    float q = (qa + qb) + (qc + qd);
    float r = rsqrtf(q * (1.0f / 64.0f) + 1e-5f);

    ull r2 = pk2(r, r);
    #pragma unroll
    for (int l = 0; l < 32; l++) {
        ull tnorm = fmul2(y2[l], r2);
        ull a2    = ffma2(tnorm, sgx2[l], sbxg2[l]);
        float a0, a1; upk2(a0, a1, a2);
        stage[wrp][lane][l] = make_float2(a0, a1);
    }
    __syncwarp();

    float2* gax2 = (float2*)g_ax;
    #pragma unroll 4
    for (int k = 0; k < 32; k++) {
        int tk = tbase + k;
        if (tk < T_STEPS)
            gax2[((size_t)tk * 256 + b) * 32 + lane] = stage[wrp][k][lane];
    }
}

// ---------------------------------------------------------------------------
// Sequential LSTM scan, TWO rows per warp, software-pipelined: row B's
// instructions fill row A's latency bubbles (smem roundtrips, MUFU, SHFL).
// Per row: lane l owns gate rows l (i|f) and l+32 (g|o); c/h on upper lanes.
// LN64 mean folded into centered WhC; var + LN16 stats via smem gathers
// shared across both rows (one syncwarp covers both).
// ---------------------------------------------------------------------------
__global__ void __launch_bounds__(32) lstm_seq_kernel(
    const float* __restrict__ gh,   const float* __restrict__ bh,
    const float* __restrict__ gc,   const float* __restrict__ bc,
    const float* __restrict__ Wcls, const float* __restrict__ bcls,
    const float* __restrict__ h0,   const float* __restrict__ c0,
    float* __restrict__ out)
{
    const unsigned ALL = 0xffffffffu;
    int lane  = threadIdx.x;
    int m     = lane & 15;
    bool upper = lane >= 16;
    int rowA  = blockIdx.x * 2;
    int rowB  = rowA + 1;

    __shared__ float  shv[2][16];   // h broadcast per row
    __shared__ float  sqp[2][32];   // q partials per row
    __shared__ float2 scq[2][16];   // (c, c^2) per row

    // shared weights (identical for both rows)
    float wa[16], wb[16];
    #pragma unroll
    for (int i = 0; i < 16; i++) {
        wa[i] = g_WhC[lane * 16 + i];
        wb[i] = g_WhC[(lane + 32) * 16 + i];
    }
    float gha = gh[lane], ghb = gh[lane + 32];
    float bha = bh[lane], bhb = bh[lane + 32];
    float gcm = gc[m],    bcm = bc[m];

    float hA = h0[rowA * 16 + m], cA = c0[rowA * 16 + m];
    float hB = h0[rowB * 16 + m], cB = c0[rowB * 16 + m];
    if (upper) { shv[0][m] = hA; shv[1][m] = hB; }
    __syncwarp();

    const float2* ax = (const float2*)g_ax;
    int baseA = rowA * 32 + lane;
    int baseB = rowB * 32 + lane;
    const int stride = BATCH * 32;
    float2 p0A = ax[baseA],          p0B = ax[baseB];
    float2 p1A = ax[baseA + stride], p1B = ax[baseB + stride];

    for (int t = 0; t < T_STEPS; t++) {
        // --- h broadcasts (LDS.128, conflict-free broadcast) ---
        const float4* hbA = (const float4*)shv[0];
        const float4* hbB = (const float4*)shv[1];
        float4 A0 = hbA[0], A1 = hbA[1], A2 = hbA[2], A3 = hbA[3];
        float4 B0 = hbB[0], B1 = hbB[1], B2 = hbB[2], B3 = hbB[3];

        float2 curA = p0A; p0A = p1A;
        float2 curB = p0B; p0B = p1B;
        if (t + 2 < T_STEPS) {
            p1A = ax[baseA + (t + 2) * stride];
            p1B = ax[baseB + (t + 2) * stride];
        }

        // --- centered matvecs, interleaved A/B (8 independent FMA chains) ---
        float yAa0, yAa1, yAb0, yAb1, yBa0, yBa1, yBb0, yBb1;
        yAa0 = wa[0]*A0.x; yAa1 = wa[1]*A0.y; yAb0 = wb[0]*A0.x; yAb1 = wb[1]*A0.y;
        yBa0 = wa[0]*B0.x; yBa1 = wa[1]*B0.y; yBb0 = wb[0]*B0.x; yBb1 = wb[1]*B0.y;
        yAa0 = fmaf(wa[2],  A0.z, yAa0); yAa1 = fmaf(wa[3],  A0.w, yAa1);
        yAb0 = fmaf(wb[2],  A0.z, yAb0); yAb1 = fmaf(wb[3],  A0.w, yAb1);
        yBa0 = fmaf(wa[2],  B0.z, yBa0); yBa1 = fmaf(wa[3],  B0.w, yBa1);
        yBb0 = fmaf(wb[2],  B0.z, yBb0); yBb1 = fmaf(wb[3],  B0.w, yBb1);
        yAa0 = fmaf(wa[4],  A1.x, yAa0); yAa1 = fmaf(wa[5],  A1.y, yAa1);
        yAb0 = fmaf(wb[4],  A1.x, yAb0); yAb1 = fmaf(wb[5],  A1.y, yAb1);
        yBa0 = fmaf(wa[4],  B1.x, yBa0); yBa1 = fmaf(wa[5],  B1.y, yBa1);
        yBb0 = fmaf(wb[4],  B1.x, yBb0); yBb1 = fmaf(wb[5],  B1.y, yBb1);
        yAa0 = fmaf(wa[6],  A1.z, yAa0); yAa1 = fmaf(wa[7],  A1.w, yAa1);
        yAb0 = fmaf(wb[6],  A1.z, yAb0); yAb1 = fmaf(wb[7],  A1.w, yAb1);
        yBa0 = fmaf(wa[6],  B1.z, yBa0); yBa1 = fmaf(wa[7],  B1.w, yBa1);
        yBb0 = fmaf(wb[6],  B1.z, yBb0); yBb1 = fmaf(wb[7],  B1.w, yBb1);
        yAa0 = fmaf(wa[8],  A2.x, yAa0); yAa1 = fmaf(wa[9],  A2.y, yAa1);
        yAb0 = fmaf(wb[8],  A2.x, yAb0); yAb1 = fmaf(wb[9],  A2.y, yAb1);
        yBa0 = fmaf(wa[8],  B2.x, yBa0); yBa1 = fmaf(wa[9],  B2.y, yBa1);
        yBb0 = fmaf(wb[8],  B2.x, yBb0); yBb1 = fmaf(wb[9],  B2.y, yBb1);
        yAa0 = fmaf(wa[10], A2.z, yAa0); yAa1 = fmaf(wa[11], A2.w, yAa1);
        yAb0 = fmaf(wb[10], A2.z, yAb0); yAb1 = fmaf(wb[11], A2.w, yAb1);
        yBa0 = fmaf(wa[10], B2.z, yBa0); yBa1 = fmaf(wa[11], B2.w, yBa1);
        yBb0 = fmaf(wb[10], B2.z, yBb0); yBb1 = fmaf(wb[11], B2.w, yBb1);
        yAa0 = fmaf(wa[12], A3.x, yAa0); yAa1 = fmaf(wa[13], A3.y, yAa1);
        yAb0 = fmaf(wb[12], A3.x, yAb0); yAb1 = fmaf(wb[13], A3.y, yAb1);
        yBa0 = fmaf(wa[12], B3.x, yBa0); yBa1 = fmaf(wa[13], B3.y, yBa1);
        yBb0 = fmaf(wb[12], B3.x, yBb0); yBb1 = fmaf(wb[13], B3.y, yBb1);
        yAa0 = fmaf(wa[14], A3.z, yAa0); yAa1 = fmaf(wa[15], A3.w, yAa1);
        yAb0 = fmaf(wb[14], A3.z, yAb0); yAb1 = fmaf(wb[15], A3.w, yAb1);
        yBa0 = fmaf(wa[14], B3.z, yBa0); yBa1 = fmaf(wa[15], B3.w, yBa1);
        yBb0 = fmaf(wb[14], B3.z, yBb0); yBb1 = fmaf(wb[15], B3.w, yBb1);
        float yAa = yAa0 + yAa1, yAb = yAb0 + yAb1;
        float yBa = yBa0 + yBa1, yBb = yBb0 + yBb1;

        // --- var partials for both rows; one syncwarp ---
        sqp[0][lane] = fmaf(yAa, yAa, yAb * yAb);
        sqp[1][lane] = fmaf(yBa, yBa, yBb * yBb);
        __syncwarp();

        const ull* qvA = (const ull*)sqp[0];
        const ull* qvB = (const ull*)sqp[1];
        ull tA0 = fadd2(qvA[0],  qvA[1]);
        ull tA1 = fadd2(qvA[2],  qvA[3]);
        ull tA2 = fadd2(qvA[4],  qvA[5]);
        ull tA3 = fadd2(qvA[6],  qvA[7]);
        ull tA4 = fadd2(qvA[8],  qvA[9]);
        ull tA5 = fadd2(qvA[10], qvA[11]);
        ull tA6 = fadd2(qvA[12], qvA[13]);
        ull tA7 = fadd2(qvA[14], qvA[15]);
        ull tB0 = fadd2(qvB[0],  qvB[1]);
        ull tB1 = fadd2(qvB[2],  qvB[3]);
        ull tB2 = fadd2(qvB[4],  qvB[5]);
        ull tB3 = fadd2(qvB[6],  qvB[7]);
        ull tB4 = fadd2(qvB[8],  qvB[9]);
        ull tB5 = fadd2(qvB[10], qvB[11]);
        ull tB6 = fadd2(qvB[12], qvB[13]);
        ull tB7 = fadd2(qvB[14], qvB[15]);
        tA0 = fadd2(tA0, tA1); tA2 = fadd2(tA2, tA3);
        tA4 = fadd2(tA4, tA5); tA6 = fadd2(tA6, tA7);
        tB0 = fadd2(tB0, tB1); tB2 = fadd2(tB2, tB3);
        tB4 = fadd2(tB4, tB5); tB6 = fadd2(tB6, tB7);
        tA0 = fadd2(fadd2(tA0, tA2), fadd2(tA4, tA6));
        tB0 = fadd2(fadd2(tB0, tB2), fadd2(tB4, tB6));
        float qAl, qAh, qBl, qBh;
        upk2(qAl, qAh, tA0); upk2(qBl, qBh, tB0);
        float rA = rsqrtf((qAl + qAh) * (1.0f / 64.0f) + 1e-5f);
        float rB = rsqrtf((qBl + qBh) * (1.0f / 64.0f) + 1e-5f);

        float gaA = fmaf(yAa * rA, gha, bha) + curA.x;
        float gbA = fmaf(yAb * rA, ghb, bhb) + curA.y;
        float gaB = fmaf(yBa * rB, gha, bha) + curB.x;
        float gbB = fmaf(yBb * rB, ghb, bhb) + curB.y;

        float u1A = sigf(gaA);
        float u1B = sigf(gaB);
        float u2A = sigf(upper ? gbA : (2.0f * gbA));
        float u2B = sigf(upper ? gbB : (2.0f * gbB));
        float AvA = u1A * fmaf(2.0f, u2A, -1.0f);
        float AvB = u1B * fmaf(2.0f, u2B, -1.0f);
        float AA = __shfl_xor_sync(ALL, AvA, 16);
        float AB = __shfl_xor_sync(ALL, AvB, 16);

        cA = fmaf(u1A, cA, AA);
        cB = fmaf(u1B, cB, AB);
        if (upper) {
            scq[0][m] = make_float2(cA, cA * cA);
            scq[1][m] = make_float2(cB, cB * cB);
        }
        __syncwarp();

        // --- LN16 stats for both rows (fused sum/sumsq trees) ---
        const ull* cvA = (const ull*)scq[0];
        const ull* cvB = (const ull*)scq[1];
        ull sA0 = fadd2(cvA[0],  cvA[1]);
        ull sA1 = fadd2(cvA[2],  cvA[3]);
        ull sA2 = fadd2(cvA[4],  cvA[5]);
        ull sA3 = fadd2(cvA[6],  cvA[7]);
        ull sA4 = fadd2(cvA[8],  cvA[9]);
        ull sA5 = fadd2(cvA[10], cvA[11]);
        ull sA6 = fadd2(cvA[12], cvA[13]);
        ull sA7 = fadd2(cvA[14], cvA[15]);
        ull sB0 = fadd2(cvB[0],  cvB[1]);
        ull sB1 = fadd2(cvB[2],  cvB[3]);
        ull sB2 = fadd2(cvB[4],  cvB[5]);
        ull sB3 = fadd2(cvB[6],  cvB[7]);
        ull sB4 = fadd2(cvB[8],  cvB[9]);
        ull sB5 = fadd2(cvB[10], cvB[11]);
        ull sB6 = fadd2(cvB[12], cvB[13]);
        ull sB7 = fadd2(cvB[14], cvB[15]);
        sA0 = fadd2(sA0, sA1); sA2 = fadd2(sA2, sA3);
        sA4 = fadd2(sA4, sA5); sA6 = fadd2(sA6, sA7);
        sB0 = fadd2(sB0, sB1); sB2 = fadd2(sB2, sB3);
        sB4 = fadd2(sB4, sB5); sB6 = fadd2(sB6, sB7);
        sA0 = fadd2(fadd2(sA0, sA2), fadd2(sA4, sA6));
        sB0 = fadd2(fadd2(sB0, sB2), fadd2(sB4, sB6));
        float scA, qcA, scB, qcB;
        upk2(scA, qcA, sA0); upk2(scB, qcB, sB0);

        float mcA = scA * (1.0f / 16.0f);
        float mcB = scB * (1.0f / 16.0f);
        float vcA = fmaf(-mcA, mcA, qcA * (1.0f / 16.0f));
        float vcB = fmaf(-mcB, mcB, qcB * (1.0f / 16.0f));
        float rcA = rsqrtf(vcA + 1e-5f);
        float rcB = rsqrtf(vcB + 1e-5f);
        float cnA = fmaf((cA - mcA) * rcA, gcm, bcm);
        float cnB = fmaf((cB - mcB) * rcB, gcm, bcm);
        float uA = sigf(2.0f * cnA);              // tanh = 2u-1
        float uB = sigf(2.0f * cnB);
        hA = fmaf(u2A + u2A, uA, -u2A);
        hB = fmaf(u2B + u2B, uB, -u2B);
        if (upper) { shv[0][m] = hA; shv[1][m] = hB; }
        __syncwarp();
    }

    // classifier for both rows
    float vA = upper ? hA * Wcls[m] : 0.0f;
    float vB = upper ? hB * Wcls[m] : 0.0f;
    #pragma unroll
    for (int d = 16; d >= 1; d >>= 1) {
        vA += __shfl_xor_sync(ALL, vA, d);
        vB += __shfl_xor_sync(ALL, vB, d);
    }
    if (lane == 0) {
        out[rowA] = sigf(vA + bcls[0]);
        out[rowB] = sigf(vB + bcls[0]);
    }
}

// ---------------------------------------------------------------------------
extern "C" void kernel_launch(void* const* d_in, const int* in_sizes, int n_in,
                              void* d_out, int out_size)
{
    const float* x     = (const float*)d_in[0];
    const float* Wm    = (const float*)d_in[1];
    const float* bm    = (const float*)d_in[2];
    const float* Wc    = (const float*)d_in[3];
    const float* bconv = (const float*)d_in[4];
    const float* Wx    = (const float*)d_in[5];
    const float* Wh    = (const float*)d_in[6];
    const float* bg    = (const float*)d_in[7];
    const float* gx    = (const float*)d_in[8];
    const float* bx    = (const float*)d_in[9];
    const float* gh    = (const float*)d_in[10];
    const float* bh    = (const float*)d_in[11];
    const float* gc    = (const float*)d_in[12];
    const float* bc    = (const float*)d_in[13];
    const float* Wcls  = (const float*)d_in[14];
    const float* bcls  = (const float*)d_in[15];
    const float* h0    = (const float*)d_in[16];
    const float* c0    = (const float*)d_in[17];
    float* out = (float*)d_out;

    init_kernel<<<1, 128>>>(Wm, bm, Wc, Wh, Wx);
    dim3 pgrid((T_STEPS + 127) / 128, BATCH);
    prepass_kernel<<<pgrid, 128>>>(x, Wm, bm, Wc, bconv, gx, bx, bg);
    lstm_seq_kernel<<<BATCH / 2, 32>>>(gh, bh, gc, bc, Wcls, bcls, h0, c0, out);
}

// round 8
// speedup vs baseline: 1.0685x; 1.0546x over previous
#include <cuda_runtime.h>

#define T_STEPS 2000
#define BATCH   256
#define SEQ     10000
#define KW      5

typedef unsigned long long ull;

// Gate pre-activations a_x[t][b][j], stored so float2 at (t*256+b)*32 + l =
// { a[j=l], a[j=l+32] } (lane l of scan warp owns gate rows l and l+32).
__device__ float g_ax[(size_t)T_STEPS * BATCH * 64];

__device__ __forceinline__ float tanhap(float x) {
    float r; asm("tanh.approx.f32 %0, %1;" : "=f"(r) : "f"(x)); return r;
}

// ---- f32x2 packed helpers (sm_103a) --------------------------------------
__device__ __forceinline__ ull pk2(float lo, float hi) {
    ull r; asm("mov.b64 %0, {%1, %2};" : "=l"(r) : "f"(lo), "f"(hi)); return r;
}
__device__ __forceinline__ void upk2(float& lo, float& hi, ull v) {
    asm("mov.b64 {%0, %1}, %2;" : "=f"(lo), "=f"(hi) : "l"(v));
}
__device__ __forceinline__ ull ffma2(ull a, ull b, ull c) {
    ull r; asm("fma.rn.f32x2 %0, %1, %2, %3;" : "=l"(r) : "l"(a), "l"(b), "l"(c)); return r;
}
__device__ __forceinline__ ull fadd2(ull a, ull b) {
    ull r; asm("add.rn.f32x2 %0, %1, %2;" : "=l"(r) : "l"(a), "l"(b)); return r;
}
__device__ __forceinline__ ull fmul2(ull a, ull b) {
    ull r; asm("mul.rn.f32x2 %0, %1, %2;" : "=l"(r) : "l"(a), "l"(b)); return r;
}

__device__ __forceinline__ float sigf_exact(float x) {
    return __fdividef(1.0f, 1.0f + __expf(-x));
}

// ---------------------------------------------------------------------------
// Pre-pass: one THREAD per (t, b); warp covers 32 consecutive t of one b.
// Self-contained: computes P/N conv-collapse and Wx column means in-block
// (no separate init kernel). Centered WxC -> no LN mean reduction.
// ---------------------------------------------------------------------------
__global__ void __launch_bounds__(128) prepass_kernel(
    const float* __restrict__ x,  const float* __restrict__ Wm,
    const float* __restrict__ bm, const float* __restrict__ Wc,
    const float* __restrict__ bconv, const float* __restrict__ Wx,
    const float* __restrict__ gx, const float* __restrict__ bx,
    const float* __restrict__ bg)
{
    __shared__ float sP[80], sN[80], sbc[16];
    __shared__ float sWm[16], sbm[16], scmx[16];
    __shared__ int   sbmnz;
    __shared__ float sWcT[80 * 16];                 // fallback path only
    __shared__ ull sWxT2[16][32];                   // [o][l] = (WxC[l][o], WxC[l+32][o])
    __shared__ ull sgx2[32], sbxg2[32];
    __shared__ float2 stage[4][32][33];             // [warp][item][pair] (+pad)

    // --- phase 0: P/N, bmnz flag, Wx column means ---
    if (threadIdx.x == 0) {
        int nz = 0;
        for (int i = 0; i < 16; i++) if (bm[i] != 0.0f) nz = 1;
        sbmnz = nz;
    }
    if (threadIdx.x < 80) {
        int o = threadIdx.x / 5, k = threadIdx.x % 5;
        float p = 0.0f, n = 0.0f;
        for (int i = 0; i < 16; i++) {
            float w = __ldg(&Wm[i]);
            float c = __ldg(&Wc[o * 80 + i * 5 + k]);
            if (w > 0.0f) p = fmaf(c, w, p);
            else if (w < 0.0f) n = fmaf(c, w, n);
        }
        sP[threadIdx.x] = p;
        sN[threadIdx.x] = n;
    }
    if (threadIdx.x >= 96 && threadIdx.x < 112) {
        int col = threadIdx.x - 96;
        float s = 0.0f;
        for (int j = 0; j < 64; j++) s += __ldg(&Wx[j * 16 + col]);
        scmx[col] = s * (1.0f / 64.0f);
    }
    for (int i = threadIdx.x; i < 16; i += blockDim.x) {
        sbc[i] = bconv[i]; sWm[i] = Wm[i]; sbm[i] = bm[i];
    }
    for (int i = threadIdx.x; i < 80 * 16; i += blockDim.x) {
        int ik = i >> 4, o = i & 15;
        sWcT[i] = Wc[o * 80 + ik];
    }
    for (int i = threadIdx.x; i < 32; i += blockDim.x) {
        sgx2[i]  = pk2(gx[i], gx[i + 32]);
        sbxg2[i] = pk2(bx[i] + bg[i], bx[i + 32] + bg[i + 32]);
    }
    __syncthreads();

    // --- phase 1: centered, packed Wx ---
    for (int i = threadIdx.x; i < 16 * 32; i += blockDim.x) {
        int o = i >> 5, l = i & 31;
        sWxT2[o][l] = pk2(Wx[l * 16 + o] - scmx[o],
                          Wx[(l + 32) * 16 + o] - scmx[o]);
    }
    __syncthreads();

    const int bmnz = sbmnz;
    int lane = threadIdx.x & 31;
    int wrp  = threadIdx.x >> 5;
    int b    = blockIdx.y;
    int tbase = blockIdx.x * 128 + wrp * 32;
    int t     = tbase + lane;
    int tt = (t < T_STEPS) ? t : 0;

    float xt[16];
    #pragma unroll
    for (int o = 0; o < 16; o++) xt[o] = sbc[o];

    if (!bmnz) {
        #pragma unroll
        for (int k = 0; k < KW; k++) {
            float xk = __ldg(&x[b * SEQ + tt * KW + k]);
            const float* PN = (xk > 0.0f) ? sP : sN;
            #pragma unroll
            for (int o = 0; o < 16; o++)
                xt[o] = fmaf(xk, PN[o * 5 + k], xt[o]);
        }
    } else {
        #pragma unroll
        for (int k = 0; k < KW; k++) {
            float xk = __ldg(&x[b * SEQ + tt * KW + k]);
            #pragma unroll
            for (int i = 0; i < 16; i++) {
                float f = fmaxf(fmaf(xk, sWm[i], sbm[i]), 0.0f);
                const float4* wr = (const float4*)&sWcT[(i * KW + k) * 16];
                #pragma unroll
                for (int o4 = 0; o4 < 4; o4++) {
                    float4 w = wr[o4];
                    xt[o4 * 4 + 0] = fmaf(w.x, f, xt[o4 * 4 + 0]);
                    xt[o4 * 4 + 1] = fmaf(w.y, f, xt[o4 * 4 + 1]);
                    xt[o4 * 4 + 2] = fmaf(w.z, f, xt[o4 * 4 + 2]);
                    xt[o4 * 4 + 3] = fmaf(w.w, f, xt[o4 * 4 + 3]);
                }
            }
        }
    }
    // exact sigmoid here (prepass is parallel; accuracy over speed)
    #pragma unroll
    for (int o = 0; o < 16; o++) xt[o] = sigf_exact(xt[o]);

    // y' = xt @ WxC^T, packed; mean(y') == 0 by construction
    ull y2[32];
    #pragma unroll
    for (int l = 0; l < 32; l++) y2[l] = 0ull;
    #pragma unroll
    for (int o = 0; o < 16; o++) {
        ull x2 = pk2(xt[o], xt[o]);
        #pragma unroll
        for (int l = 0; l < 32; l++)
            y2[l] = ffma2(sWxT2[o][l], x2, y2[l]);
    }

    ull q2a = 0ull, q2b = 0ull;
    #pragma unroll
    for (int l = 0; l < 32; l += 2) {
        q2a = ffma2(y2[l],     y2[l],     q2a);
        q2b = ffma2(y2[l + 1], y2[l + 1], q2b);
    }
    float qa, qb, qc, qd;
    upk2(qa, qb, q2a); upk2(qc, qd, q2b);
    float q = (qa + qb) + (qc + qd);
    float r = rsqrtf(q * (1.0f / 64.0f) + 1e-5f);

    ull r2 = pk2(r, r);
    #pragma unroll
    for (int l = 0; l < 32; l++) {
        ull tnorm = fmul2(y2[l], r2);
        ull a2    = ffma2(tnorm, sgx2[l], sbxg2[l]);
        float a0, a1; upk2(a0, a1, a2);
        stage[wrp][lane][l] = make_float2(a0, a1);
    }
    __syncwarp();

    float2* gax2 = (float2*)g_ax;
    #pragma unroll 4
    for (int k = 0; k < 32; k++) {
        int tk = tbase + k;
        if (tk < T_STEPS)
            gax2[((size_t)tk * 256 + b) * 32 + lane] = stage[wrp][k][lane];
    }
}

// ---------------------------------------------------------------------------
// Sequential LSTM scan. ONE warp = ONE batch row (wallclock = T * chain, so
// chain length is everything). lane l owns gate rows l (i|f), l+32 (g|o);
// c/h state on upper 16 lanes. WhC centered in a one-time prologue (LN64
// mean folded into weights). All nonlinearities via single-MUFU tanh.approx.
// ---------------------------------------------------------------------------
__global__ void __launch_bounds__(32) lstm_seq_kernel(
    const float* __restrict__ Wh,   const float* __restrict__ gh,
    const float* __restrict__ bh,   const float* __restrict__ gc,
    const float* __restrict__ bc,   const float* __restrict__ Wcls,
    const float* __restrict__ bcls, const float* __restrict__ h0,
    const float* __restrict__ c0,   float* __restrict__ out)
{
    const unsigned ALL = 0xffffffffu;
    int lane  = threadIdx.x;
    int m     = lane & 15;
    bool upper = lane >= 16;
    int row   = blockIdx.x;

    __shared__ float  smean[16];  // Wh column means
    __shared__ float  shv[16];    // h broadcast
    __shared__ float  sqp[32];    // q partials
    __shared__ float2 scq[16];    // (c, c^2)

    // prologue: column means of Wh (lanes 0..15 own col m; 16..31 redundant)
    {
        float s = 0.0f;
        #pragma unroll 8
        for (int j = 0; j < 64; j++) s += __ldg(&Wh[j * 16 + m]);
        if (!upper) smean[m] = s * (1.0f / 64.0f);
    }
    __syncwarp();

    float wa[16], wb[16];
    #pragma unroll
    for (int i = 0; i < 16; i++) {
        float cm = smean[i];
        wa[i] = __ldg(&Wh[lane * 16 + i]) - cm;
        wb[i] = __ldg(&Wh[(lane + 32) * 16 + i]) - cm;
    }
    float gha = gh[lane], ghb = gh[lane + 32];
    float bha = bh[lane], bhb = bh[lane + 32];
    float gcm = gc[m],    bcm = bc[m];

    float h = h0[row * 16 + m];
    float c = c0[row * 16 + m];
    if (upper) shv[m] = h;
    __syncwarp();

    const float2* ax = (const float2*)g_ax;
    int base = row * 32 + lane;
    const int stride = BATCH * 32;
    float2 p0 = ax[base];
    float2 p1 = ax[base + stride];

    for (int t = 0; t < T_STEPS; t++) {
        // --- h broadcast (LDS.128 broadcast, conflict-free) ---
        const float4* hb = (const float4*)shv;
        float4 hv0 = hb[0], hv1 = hb[1], hv2 = hb[2], hv3 = hb[3];

        float2 cur = p0;
        p0 = p1;
        if (t + 2 < T_STEPS) p1 = ax[base + (t + 2) * stride];

        // --- centered matvec (4 independent FMA chains) ---
        float ya0, ya1, yb0, yb1;
        ya0 = wa[0] * hv0.x; ya1 = wa[1] * hv0.y;
        yb0 = wb[0] * hv0.x; yb1 = wb[1] * hv0.y;
        ya0 = fmaf(wa[2],  hv0.z, ya0); ya1 = fmaf(wa[3],  hv0.w, ya1);
        yb0 = fmaf(wb[2],  hv0.z, yb0); yb1 = fmaf(wb[3],  hv0.w, yb1);
        ya0 = fmaf(wa[4],  hv1.x, ya0); ya1 = fmaf(wa[5],  hv1.y, ya1);
        yb0 = fmaf(wb[4],  hv1.x, yb0); yb1 = fmaf(wb[5],  hv1.y, yb1);
        ya0 = fmaf(wa[6],  hv1.z, ya0); ya1 = fmaf(wa[7],  hv1.w, ya1);
        yb0 = fmaf(wb[6],  hv1.z, yb0); yb1 = fmaf(wb[7],  hv1.w, yb1);
        ya0 = fmaf(wa[8],  hv2.x, ya0); ya1 = fmaf(wa[9],  hv2.y, ya1);
        yb0 = fmaf(wb[8],  hv2.x, yb0); yb1 = fmaf(wb[9],  hv2.y, yb1);
        ya0 = fmaf(wa[10], hv2.z, ya0); ya1 = fmaf(wa[11], hv2.w, ya1);
        yb0 = fmaf(wb[10], hv2.z, yb0); yb1 = fmaf(wb[11], hv2.w, yb1);
        ya0 = fmaf(wa[12], hv3.x, ya0); ya1 = fmaf(wa[13], hv3.y, ya1);
        yb0 = fmaf(wb[12], hv3.x, yb0); yb1 = fmaf(wb[13], hv3.y, yb1);
        ya0 = fmaf(wa[14], hv3.z, ya0); ya1 = fmaf(wa[15], hv3.w, ya1);
        yb0 = fmaf(wb[14], hv3.z, yb0); yb1 = fmaf(wb[15], hv3.w, yb1);
        float ya = ya0 + ya1;
        float yb = yb0 + yb1;

        // --- var reduction via smem gather (mean == 0 by construction) ---
        sqp[lane] = fmaf(ya, ya, yb * yb);
        __syncwarp();
        const ull* qv = (const ull*)sqp;
        ull t0 = fadd2(qv[0],  qv[1]);
        ull t1 = fadd2(qv[2],  qv[3]);
        ull t2 = fadd2(qv[4],  qv[5]);
        ull t3 = fadd2(qv[6],  qv[7]);
        ull t4 = fadd2(qv[8],  qv[9]);
        ull t5 = fadd2(qv[10], qv[11]);
        ull t6 = fadd2(qv[12], qv[13]);
        ull t7 = fadd2(qv[14], qv[15]);
        t0 = fadd2(t0, t1); t2 = fadd2(t2, t3);
        t4 = fadd2(t4, t5); t6 = fadd2(t6, t7);
        t0 = fadd2(fadd2(t0, t2), fadd2(t4, t6));
        float qlo, qhi; upk2(qlo, qhi, t0);
        float r = rsqrtf((qlo + qhi) * (1.0f / 64.0f) + 1e-5f);

        float ga = fmaf(ya * r, gha, bha) + cur.x;   // i | f
        float gb = fmaf(yb * r, ghb, bhb) + cur.y;   // g | o

        // single-MUFU nonlinearities: sig(x) = 0.5*tanh(0.5x)+0.5
        float u1 = fmaf(0.5f, tanhap(0.5f * ga), 0.5f);   // sig(i) | sig(f)
        float tb = tanhap(upper ? (0.5f * gb) : gb);
        float u2 = upper ? fmaf(0.5f, tb, 0.5f) : tb;     // sig(o) | tanh(g)
        float Aval = u1 * u2;                             // lower: sig(i)*tanh(g)
        float A = __shfl_xor_sync(ALL, Aval, 16);

        c = fmaf(u1, c, A);                               // valid on upper lanes
        if (upper) scq[m] = make_float2(c, c * c);
        __syncwarp();

        // --- LN16 stats: one fadd2 tree -> (sum, sumsq) ---
        const ull* cv = (const ull*)scq;
        ull s0 = fadd2(cv[0],  cv[1]);
        ull s1 = fadd2(cv[2],  cv[3]);
        ull s2 = fadd2(cv[4],  cv[5]);
        ull s3 = fadd2(cv[6],  cv[7]);
        ull s4 = fadd2(cv[8],  cv[9]);
        ull s5 = fadd2(cv[10], cv[11]);
        ull s6 = fadd2(cv[12], cv[13]);
        ull s7 = fadd2(cv[14], cv[15]);
        s0 = fadd2(s0, s1); s2 = fadd2(s2, s3);
        s4 = fadd2(s4, s5); s6 = fadd2(s6, s7);
        s0 = fadd2(fadd2(s0, s2), fadd2(s4, s6));
        float sc, qc; upk2(sc, qc, s0);

        float mc = sc * (1.0f / 16.0f);
        float vc = fmaf(-mc, mc, qc * (1.0f / 16.0f));
        float rc = rsqrtf(vc + 1e-5f);
        float cn = fmaf((c - mc) * rc, gcm, bcm);
        h = u2 * tanhap(cn);                              // sig(o)*tanh(cn), upper
        if (upper) shv[m] = h;
        __syncwarp();
    }

    // classifier: sigmoid(h . W_cls + b_cls)  (h valid on upper lanes)
    float v = upper ? h * Wcls[m] : 0.0f;
    #pragma unroll
    for (int d = 16; d >= 1; d >>= 1)
        v += __shfl_xor_sync(ALL, v, d);
    if (lane == 0)
        out[row] = sigf_exact(v + bcls[0]);
}

// ---------------------------------------------------------------------------
extern "C" void kernel_launch(void* const* d_in, const int* in_sizes, int n_in,
                              void* d_out, int out_size)
{
    const float* x     = (const float*)d_in[0];
    const float* Wm    = (const float*)d_in[1];
    const float* bm    = (const float*)d_in[2];
    const float* Wc    = (const float*)d_in[3];
    const float* bconv = (const float*)d_in[4];
    const float* Wx    = (const float*)d_in[5];
    const float* Wh    = (const float*)d_in[6];
    const float* bg    = (const float*)d_in[7];
    const float* gx    = (const float*)d_in[8];
    const float* bx    = (const float*)d_in[9];
    const float* gh    = (const float*)d_in[10];
    const float* bh    = (const float*)d_in[11];
    const float* gc    = (const float*)d_in[12];
    const float* bc    = (const float*)d_in[13];
    const float* Wcls  = (const float*)d_in[14];
    const float* bcls  = (const float*)d_in[15];
    const float* h0    = (const float*)d_in[16];
    const float* c0    = (const float*)d_in[17];
    float* out = (float*)d_out;

    dim3 pgrid((T_STEPS + 127) / 128, BATCH);
    prepass_kernel<<<pgrid, 128>>>(x, Wm, bm, Wc, bconv, Wx, gx, bx, bg);
    lstm_seq_kernel<<<BATCH, 32>>>(Wh, gh, bh, gc, bc, Wcls, bcls, h0, c0, out);
}